// round 9
// baseline (speedup 1.0000x reference)
#include <cuda_runtime.h>

#define NPTS 300000
#define NBLK 1172   // ceil(NPTS / 256)

// ---------------- scratch (static device globals; no allocation) ----------------
__device__ float g_h[NPTS * 32];                 // bottleneck activations [N,32]
__device__ float g_ms[(size_t)NPTS * 192];       // concat(feat1,feat2,feat3) [N,192]
__device__ float g_pooled[192];                  // global max pool
__device__ float g_wf[192 * 64];                 // attn-scaled fusion weights

// ---------------- packed f32x2 helpers (verified equivalent R1 vs R2/R4) ----------------
__device__ __forceinline__ unsigned long long pack2(float x) {
    unsigned long long r;
    asm("mov.b64 %0, {%1, %1};" : "=l"(r) : "f"(x));
    return r;
}
__device__ __forceinline__ void ffma2(unsigned long long &d,
                                      unsigned long long a,
                                      unsigned long long b) {
    asm("fma.rn.f32x2 %0, %1, %2, %0;" : "+l"(d) : "l"(a), "l"(b));
}
__device__ __forceinline__ float lo32(unsigned long long v) {
    return __uint_as_float((unsigned)(v & 0xffffffffull));
}
__device__ __forceinline__ float hi32(unsigned long long v) {
    return __uint_as_float((unsigned)(v >> 32));
}

// ---------------- zero the pooled max ----------------
__global__ void k_zero() {
    g_pooled[threadIdx.x] = 0.f;
}

// ---------------- h = relu(bn2a(features @ W2a)) : [N,64]@[64,32] ----------------
__global__ __launch_bounds__(256) void k_h(const float* __restrict__ f,
                                           const float* __restrict__ W2a,
                                           const float* __restrict__ s,
                                           const float* __restrict__ b) {
    __shared__ float Ws[64 * 32];
    const int tid = threadIdx.x;
#pragma unroll
    for (int i = 0; i < 8; i++) Ws[i * 256 + tid] = W2a[i * 256 + tid];
    __syncthreads();

    const int p = blockIdx.x * 256 + tid;
    if (p >= NPTS) return;

    unsigned long long acc[16];
#pragma unroll
    for (int i = 0; i < 16; i++) acc[i] = 0ull;

    const float4* fr = (const float4*)(f + p * 64);
#pragma unroll 1
    for (int c4 = 0; c4 < 16; c4++) {
        float4 v = fr[c4];
#pragma unroll
        for (int cc = 0; cc < 4; cc++) {
            unsigned long long g2 = pack2((&v.x)[cc]);
            const ulonglong2* wr = (const ulonglong2*)(Ws + (c4 * 4 + cc) * 32);
#pragma unroll
            for (int d = 0; d < 8; d++) {
                ulonglong2 w = wr[d];
                ffma2(acc[2 * d],     w.x, g2);
                ffma2(acc[2 * d + 1], w.y, g2);
            }
        }
    }
    float* o = g_h + p * 32;
#pragma unroll
    for (int d = 0; d < 16; d++) {
        float r0 = fmaxf(lo32(acc[d]) * s[2 * d]     + b[2 * d],     0.f);
        float r1 = fmaxf(hi32(acc[d]) * s[2 * d + 1] + b[2 * d + 1], 0.f);
        *(float2*)(o + 2 * d) = make_float2(r0, r1);
    }
}

// ---------------- sparse conv path: ms[:,coff:+64] = relu(bn(sum_k gather_k(src)@W[k])) ----
// CTA = 128 threads, 256 points. Gathered rows staged into padded SMEM (coalesced),
// weights double-buffered in SMEM (broadcast LDS), 2 points/thread for FFMA2:LDS = 4:1.
template <int CIN>
__global__ __launch_bounds__(128, 2) void k_path(const float* __restrict__ src,
                                                 const int*   __restrict__ nbr,
                                                 const float* __restrict__ W,
                                                 const float* __restrict__ bns,
                                                 const float* __restrict__ bnb,
                                                 int coff) {
    constexpr int GSTR = CIN + 4;            // pad to kill bank conflicts
    extern __shared__ float sm[];
    float* Wb = sm;                          // [2][CIN][64]
    float* G  = sm + 2 * CIN * 64;           // [256][GSTR]

    const int tid = threadIdx.x;
    const int p0  = blockIdx.x * 256;

    unsigned long long accA[32], accB[32];
#pragma unroll
    for (int i = 0; i < 32; i++) { accA[i] = 0ull; accB[i] = 0ull; }

    // stage W[0] into buffer 0
    {
        const float4* wsrc = (const float4*)W;
        float4* wdst = (float4*)Wb;
#pragma unroll
        for (int i = 0; i < CIN / 8; i++) wdst[i * 128 + tid] = wsrc[i * 128 + tid];
    }

    for (int k = 0; k < 9; k++) {
        __syncthreads();   // previous compute done (G free), current W staged
        // ---- cooperative gather of 256 rows for this offset k ----
        {
            constexpr int TPR = CIN / 4;       // threads per row (float4 lanes)
            constexpr int RPP = 128 / TPR;     // rows per pass
            const int lane = tid % TPR;
            const int rb   = tid / TPR;
#pragma unroll
            for (int pass = 0; pass < 256 / RPP; pass++) {
                int r = pass * RPP + rb;
                int p = p0 + r;
                int idx = (p < NPTS) ? nbr[k * NPTS + p] : -1;
                float4 v = make_float4(0.f, 0.f, 0.f, 0.f);
                if (idx >= 0) v = *(const float4*)(src + (size_t)idx * CIN + lane * 4);
                *(float4*)(G + r * GSTR + lane * 4) = v;
            }
        }
        // ---- stage next k's weights into the other buffer ----
        if (k < 8) {
            const float4* wsrc = (const float4*)(W + (k + 1) * CIN * 64);
            float4* wdst = (float4*)(Wb + ((k + 1) & 1) * CIN * 64);
#pragma unroll
            for (int i = 0; i < CIN / 8; i++) wdst[i * 128 + tid] = wsrc[i * 128 + tid];
        }
        __syncthreads();
        // ---- compute: 2 points per thread, all 64 outputs ----
        const float* Wk = Wb + (k & 1) * CIN * 64;
        const float* gA = G + tid * GSTR;
        const float* gB = gA + 128 * GSTR;
#pragma unroll 1
        for (int c4 = 0; c4 < CIN / 4; c4++) {
            float4 a4 = *(const float4*)(gA + c4 * 4);
            float4 b4 = *(const float4*)(gB + c4 * 4);
#pragma unroll
            for (int cc = 0; cc < 4; cc++) {
                unsigned long long a2 = pack2((&a4.x)[cc]);
                unsigned long long b2 = pack2((&b4.x)[cc]);
                const ulonglong2* wr = (const ulonglong2*)(Wk + (c4 * 4 + cc) * 64);
#pragma unroll
                for (int d = 0; d < 16; d++) {
                    ulonglong2 w = wr[d];
                    ffma2(accA[2 * d],     w.x, a2);
                    ffma2(accA[2 * d + 1], w.y, a2);
                    ffma2(accB[2 * d],     w.x, b2);
                    ffma2(accB[2 * d + 1], w.y, b2);
                }
            }
        }
    }

    // ---- epilogue: bn + relu + store into ms ----
    {
        int pa = p0 + tid;
        if (pa < NPTS) {
            float* o = g_ms + (size_t)pa * 192 + coff;
#pragma unroll
            for (int d = 0; d < 32; d++) {
                float r0 = fmaxf(lo32(accA[d]) * bns[2 * d]     + bnb[2 * d],     0.f);
                float r1 = fmaxf(hi32(accA[d]) * bns[2 * d + 1] + bnb[2 * d + 1], 0.f);
                *(float2*)(o + 2 * d) = make_float2(r0, r1);
            }
        }
        int pb = p0 + tid + 128;
        if (pb < NPTS) {
            float* o = g_ms + (size_t)pb * 192 + coff;
#pragma unroll
            for (int d = 0; d < 32; d++) {
                float r0 = fmaxf(lo32(accB[d]) * bns[2 * d]     + bnb[2 * d],     0.f);
                float r1 = fmaxf(hi32(accB[d]) * bns[2 * d + 1] + bnb[2 * d + 1], 0.f);
                *(float2*)(o + 2 * d) = make_float2(r0, r1);
            }
        }
    }
}

// ---------------- global max pool over ms (values >= 0 post-ReLU) ----------------
__global__ __launch_bounds__(192) void k_pool() {
    const int c = threadIdx.x;
    float m = 0.f;
    for (int r = blockIdx.x; r < NPTS; r += gridDim.x)
        m = fmaxf(m, g_ms[(size_t)r * 192 + c]);
    atomicMax((int*)&g_pooled[c], __float_as_int(m));   // valid: all values >= 0
}

// ---------------- attention MLP + fold attn into Wf ----------------
// A1_w: [192,16], A1_b: [16], A2_w: [16,192], A2_b: [192]  (bottleneck = COUT/4 = 16!)
__global__ __launch_bounds__(192) void k_attn(const float* __restrict__ A1w,
                                              const float* __restrict__ A1b,
                                              const float* __restrict__ A2w,
                                              const float* __restrict__ A2b,
                                              const float* __restrict__ Wf) {
    __shared__ float sp[192], t1[16];
    const int t = threadIdx.x;
    sp[t] = g_pooled[t];
    __syncthreads();
    if (t < 16) {
        float s = A1b[t];
        for (int i = 0; i < 192; i++) s += sp[i] * A1w[i * 16 + t];
        t1[t] = fmaxf(s, 0.f);
    }
    __syncthreads();
    float s = A2b[t];
#pragma unroll
    for (int i = 0; i < 16; i++) s += t1[i] * A2w[i * 192 + t];
    float a = 1.f / (1.f + expf(-s));
    for (int d = 0; d < 64; d++) g_wf[t * 64 + d] = a * Wf[t * 64 + d];
}

// ---------------- fused = relu(bnf((ms * attn) @ Wf)) = relu(bnf(ms @ Wf')) ----------------
__global__ __launch_bounds__(256) void k_fuse(const float* __restrict__ s,
                                              const float* __restrict__ b,
                                              float* __restrict__ out) {
    extern __shared__ float Ws[];   // 192*64 scaled fusion weights
    const int tid = threadIdx.x;
#pragma unroll
    for (int i = 0; i < 12; i++)
        ((float4*)Ws)[i * 256 + tid] = ((const float4*)g_wf)[i * 256 + tid];
    __syncthreads();

    const int p = blockIdx.x * 256 + tid;
    if (p >= NPTS) return;

    unsigned long long acc[32];
#pragma unroll
    for (int i = 0; i < 32; i++) acc[i] = 0ull;

    const float4* mr = (const float4*)(g_ms + (size_t)p * 192);
#pragma unroll 1
    for (int c4 = 0; c4 < 48; c4++) {
        float4 v = mr[c4];
#pragma unroll
        for (int cc = 0; cc < 4; cc++) {
            unsigned long long g2 = pack2((&v.x)[cc]);
            const ulonglong2* wr = (const ulonglong2*)(Ws + (c4 * 4 + cc) * 64);
#pragma unroll
            for (int d = 0; d < 16; d++) {
                ulonglong2 w = wr[d];
                ffma2(acc[2 * d],     w.x, g2);
                ffma2(acc[2 * d + 1], w.y, g2);
            }
        }
    }
    float* o = out + (size_t)p * 64;
#pragma unroll
    for (int d = 0; d < 32; d++) {
        float r0 = fmaxf(lo32(acc[d]) * s[2 * d]     + b[2 * d],     0.f);
        float r1 = fmaxf(hi32(acc[d]) * s[2 * d + 1] + b[2 * d + 1], 0.f);
        *(float2*)(o + 2 * d) = make_float2(r0, r1);
    }
}

// ---------------- launch ----------------
extern "C" void kernel_launch(void* const* d_in, const int* in_sizes, int n_in,
                              void* d_out, int out_size) {
    const float* features = (const float*)d_in[0];
    const float* W1    = (const float*)d_in[1];
    const float* bn1s  = (const float*)d_in[2];
    const float* bn1b  = (const float*)d_in[3];
    const float* W2a   = (const float*)d_in[4];
    const float* bn2as = (const float*)d_in[5];
    const float* bn2ab = (const float*)d_in[6];
    const float* W2b   = (const float*)d_in[7];
    const float* bn2bs = (const float*)d_in[8];
    const float* bn2bb = (const float*)d_in[9];
    const float* W3    = (const float*)d_in[10];
    const float* bn3s  = (const float*)d_in[11];
    const float* bn3b  = (const float*)d_in[12];
    const float* A1w   = (const float*)d_in[13];
    const float* A1b   = (const float*)d_in[14];
    const float* A2w   = (const float*)d_in[15];
    const float* A2b   = (const float*)d_in[16];
    const float* Wf    = (const float*)d_in[17];
    const float* bnfs  = (const float*)d_in[18];
    const float* bnfb  = (const float*)d_in[19];
    const int*   nbr1  = (const int*)d_in[20];
    const int*   nbr2  = (const int*)d_in[21];
    float* out = (float*)d_out;

    float* hptr = nullptr;
    cudaGetSymbolAddress((void**)&hptr, g_h);

    const int smem64 = 2 * 64 * 64 * 4 + 256 * 68 * 4;   // 102400
    const int smem32 = 2 * 32 * 64 * 4 + 256 * 36 * 4;   // 53248
    const int smemF  = 192 * 64 * 4;                     // 49152
    cudaFuncSetAttribute(k_path<64>, cudaFuncAttributeMaxDynamicSharedMemorySize, smem64);
    cudaFuncSetAttribute(k_path<32>, cudaFuncAttributeMaxDynamicSharedMemorySize, smem32);
    cudaFuncSetAttribute(k_fuse,     cudaFuncAttributeMaxDynamicSharedMemorySize, smemF);

    k_zero<<<1, 192>>>();
    k_h<<<NBLK, 256>>>(features, W2a, bn2as, bn2ab);
    k_path<64><<<NBLK, 128, smem64>>>(features, nbr1, W1,  bn1s,  bn1b,  0);
    k_path<32><<<NBLK, 128, smem32>>>(hptr,     nbr1, W2b, bn2bs, bn2bb, 64);
    k_path<64><<<NBLK, 128, smem64>>>(features, nbr2, W3,  bn3s,  bn3b,  128);
    k_pool<<<2048, 192>>>();
    k_attn<<<1, 192>>>(A1w, A1b, A2w, A2b, Wf);
    k_fuse<<<NBLK, 256, smemF>>>(bnfs, bnfb, out);
}